// round 15
// baseline (speedup 1.0000x reference)
#include <cuda_runtime.h>
#include <cuda_fp16.h>
#include <stdint.h>

#define BB 4
#define HH 128
#define WW 128
#define CC 1024
#define NB 8
#define BS 128
#define HID 256
#define LAM 0.01f
#define NTOT (BB*HH*WW*CC)

__device__ __align__(128) __half g_bh1[NTOT];
__device__ __align__(128) __half g_bh2[NTOT];
__device__ __align__(16) uint4 g_casPH[8*8*32];   // m16n8k16 A-fragment layout
__device__ __align__(16) __half g_w1h[NB*BS*HID];
__device__ __align__(16) __half g_w2h[NB*HID*BS];
__device__ float g_b1s[NB*HID];
__device__ float g_b2s[NB*BS];

// ---------------- helpers ----------------
__device__ __forceinline__ void mma16(float* c, uint32_t a0, uint32_t a1, uint32_t a2, uint32_t a3,
                                      uint32_t b0, uint32_t b1) {
    asm volatile("mma.sync.aligned.m16n8k16.row.col.f32.f16.f16.f32 "
                 "{%0,%1,%2,%3}, {%4,%5,%6,%7}, {%8,%9}, {%0,%1,%2,%3};"
                 : "+f"(c[0]), "+f"(c[1]), "+f"(c[2]), "+f"(c[3])
                 : "r"(a0), "r"(a1), "r"(a2), "r"(a3), "r"(b0), "r"(b1));
}
__device__ __forceinline__ void ldsm4(uint32_t* r, uint32_t a) {
    asm volatile("ldmatrix.sync.aligned.m8n8.x4.shared.b16 {%0,%1,%2,%3}, [%4];"
                 : "=r"(r[0]), "=r"(r[1]), "=r"(r[2]), "=r"(r[3]) : "r"(a));
}
__device__ __forceinline__ void ldsm4t(uint32_t* r, uint32_t a) {
    asm volatile("ldmatrix.sync.aligned.m8n8.x4.trans.shared.b16 {%0,%1,%2,%3}, [%4];"
                 : "=r"(r[0]), "=r"(r[1]), "=r"(r[2]), "=r"(r[3]) : "r"(a));
}
__device__ __forceinline__ void cp16(uint32_t saddr, const void* gptr) {
    asm volatile("cp.async.cg.shared.global [%0], [%1], 16;" :: "r"(saddr), "l"(gptr));
}
#define CP_COMMIT() asm volatile("cp.async.commit_group;")
#define CP_WAIT1()  asm volatile("cp.async.wait_group 1;" ::: "memory")
#define CP_WAIT0()  asm volatile("cp.async.wait_group 0;" ::: "memory")
__device__ __forceinline__ uint32_t sptr(const void* p) {
    return (uint32_t)__cvta_generic_to_shared(p);
}
__device__ __forceinline__ uint32_t pack2(float a, float b) {
    __half2 h = __floats2half2_rn(a, b);
    return *reinterpret_cast<uint32_t*>(&h);
}
__device__ __forceinline__ float sthr(float z) {
    return (z > LAM) ? (z - LAM) : ((z < -LAM) ? (z + LAM) : 0.f);
}

// ---------------- prep ----------------
__device__ __forceinline__ float casv(int m, int k) {
    float s, c;
    sincospif((float)((m*k) & 127) * (1.0f/64.0f), &s, &c);
    return c + s;
}
__global__ void prep_kernel(const float* __restrict__ w1, const float* __restrict__ b1,
                            const float* __restrict__ w2, const float* __restrict__ b2) {
    int t = blockIdx.x * blockDim.x + threadIdx.x;
    if (t < 8*8*32) {
        int lane = t & 31, ks = (t >> 5) & 7, mt = t >> 8;
        int g = lane >> 2, tig = lane & 3;
        int m0 = mt*16 + g, k0 = ks*16 + 2*tig;
        uint4 v;
        v.x = pack2(casv(m0, k0),     casv(m0, k0+1));
        v.y = pack2(casv(m0+8, k0),   casv(m0+8, k0+1));
        v.z = pack2(casv(m0, k0+8),   casv(m0, k0+9));
        v.w = pack2(casv(m0+8, k0+8), casv(m0+8, k0+9));
        g_casPH[t] = v;
    }
    if (t < NB*BS*HID) {
        g_w1h[t] = __float2half(w1[t] + w1[NB*BS*HID + t]);
        g_w2h[t] = __float2half(w2[t] + w2[NB*HID*BS + t]);
    }
    if (t < NB*HID) g_b1s[t] = b1[t];
    if (t < NB*BS)  g_b2s[t] = b2[t];
}

extern __shared__ uint32_t smu[];

// ---------------------------------------------------------------------------
// casmul_f2h: pass 1 (validated). OUT_h = cas @ IN_f. smem = 18432 B.
// ---------------------------------------------------------------------------
__global__ __launch_bounds__(256, 2)
void casmul_f2h(const float* __restrict__ in, __half* __restrict__ out,
                int ncols, int total) {
    char* bS = (char*)smu;
    const int tid = threadIdx.x;
    const int w = tid >> 5, lane = tid & 31;
    const int g = lane >> 2, tig = lane & 3;
    const int l15 = lane & 15, lc8 = (lane >> 4) * 8;
    const int ntn = ncols >> 6;

    uint4 A[8];
    #pragma unroll
    for (int ks = 0; ks < 8; ks++)
        A[ks] = __ldg(&g_casPH[(w*8 + ks)*32 + lane]);

    float4 pf[8];
    int t = blockIdx.x;
    {
        int bt = t / ntn, nb = t - bt*ntn;
        const float* src = in + (size_t)bt*128u*(size_t)ncols + nb*64;
        #pragma unroll
        for (int i = 0; i < 8; i++) {
            int idx = i*256 + tid, k = idx >> 4, n4 = (idx & 15) << 2;
            pf[i] = *(const float4*)(src + (size_t)k*(size_t)ncols + n4);
        }
    }

    for (; t < total; t += gridDim.x) {
        __syncthreads();
        #pragma unroll
        for (int i = 0; i < 8; i++) {
            int idx = i*256 + tid, k = idx >> 4, n4 = (idx & 15) << 2;
            uint2 u;
            u.x = pack2(pf[i].x, pf[i].y);
            u.y = pack2(pf[i].z, pf[i].w);
            *(uint2*)(bS + k*144 + n4*2) = u;
        }
        __syncthreads();

        int tn = t + gridDim.x;
        if (tn < total) {
            int bt = tn / ntn, nb = tn - bt*ntn;
            const float* src = in + (size_t)bt*128u*(size_t)ncols + nb*64;
            #pragma unroll
            for (int i = 0; i < 8; i++) {
                int idx = i*256 + tid, k = idx >> 4, n4 = (idx & 15) << 2;
                pf[i] = *(const float4*)(src + (size_t)k*(size_t)ncols + n4);
            }
        }

        float acc[8][4];
        #pragma unroll
        for (int i = 0; i < 8; i++)
            #pragma unroll
            for (int j = 0; j < 4; j++) acc[i][j] = 0.f;

        #pragma unroll
        for (int ks = 0; ks < 8; ks++) {
            #pragma unroll
            for (int nq = 0; nq < 4; nq++) {
                uint32_t b[4];
                ldsm4t(b, sptr(bS + (ks*16 + l15)*144 + (nq*16 + lc8)*2));
                mma16(acc[nq*2  ], A[ks].x, A[ks].y, A[ks].z, A[ks].w, b[0], b[1]);
                mma16(acc[nq*2+1], A[ks].x, A[ks].y, A[ks].z, A[ks].w, b[2], b[3]);
            }
        }

        __syncthreads();
        #pragma unroll
        for (int nf = 0; nf < 8; nf++)
            #pragma unroll
            for (int r = 0; r < 2; r++) {
                int row = w*16 + g + r*8;
                *(uint32_t*)(bS + row*128 + ((nf ^ g) << 4) + tig*4) =
                    pack2(acc[nf][r*2], acc[nf][r*2+1]);
            }
        __syncwarp();
        {
            int bt = t / ntn, nb = t - bt*ntn;
            const size_t base = (size_t)bt*128u*(size_t)ncols + nb*64;
            #pragma unroll
            for (int i = 0; i < 4; i++) {
                int row = w*16 + (lane >> 3) + i*4;
                int q = lane & 7;
                uint4 v = *(uint4*)(bS + row*128 + ((q ^ (row & 7)) << 4));
                *(uint4*)(out + base + (size_t)row*(size_t)ncols + q*8) = v;
            }
        }
    }
}

// ---------------------------------------------------------------------------
// casmul_h2f: pass 5 (validated). OUT_f = scale*(cas @ IN_h) + add_f.
// B + residual cp.async double-buffered. smem = 106496 B.
// ---------------------------------------------------------------------------
__global__ __launch_bounds__(256, 2)
void casmul_h2f(const __half* __restrict__ in, float* __restrict__ out,
                const float* __restrict__ addsrc, float scale, int ncols, int total) {
    char* bS0 = (char*)smu;
    char* bS1 = bS0 + 18432;
    char* rS0 = bS1 + 18432;
    char* rS1 = rS0 + 34816;
    const int tid = threadIdx.x;
    const int w = tid >> 5, lane = tid & 31;
    const int g = lane >> 2, tig = lane & 3;
    const int l15 = lane & 15, lc8 = (lane >> 4) * 8;
    const int mw = w & 3, nw = w >> 2;
    const int ntn = ncols >> 6;

    uint4 A[2][8];
    #pragma unroll
    for (int mf = 0; mf < 2; mf++)
        #pragma unroll
        for (int ks = 0; ks < 8; ks++)
            A[mf][ks] = __ldg(&g_casPH[((mw*2 + mf)*8 + ks)*32 + lane]);

    int t = blockIdx.x;
    {
        int bt = t / ntn, nb = t - bt*ntn;
        const size_t base = (size_t)bt*128u*(size_t)ncols + nb*64;
        const __half* src = in + base;
        #pragma unroll
        for (int i = 0; i < 4; i++) {
            int idx = i*256 + tid, k = idx >> 3, seg = idx & 7;
            cp16(sptr(bS0 + k*144 + seg*16), src + (size_t)k*(size_t)ncols + seg*8);
        }
        const float* rsrc = addsrc + base;
        #pragma unroll
        for (int i = 0; i < 8; i++) {
            int idx = i*256 + tid, k = idx >> 4, seg = idx & 15;
            cp16(sptr(rS0 + k*272 + seg*16), rsrc + (size_t)k*(size_t)ncols + seg*4);
        }
        CP_COMMIT();
    }

    int buf = 0;
    for (; t < total; t += gridDim.x) {
        int tn = t + gridDim.x;
        if (tn < total) {
            char* bN = buf ? bS0 : bS1;
            char* rN = buf ? rS0 : rS1;
            int bt = tn / ntn, nb = tn - bt*ntn;
            const size_t base = (size_t)bt*128u*(size_t)ncols + nb*64;
            const __half* src = in + base;
            #pragma unroll
            for (int i = 0; i < 4; i++) {
                int idx = i*256 + tid, k = idx >> 3, seg = idx & 7;
                cp16(sptr(bN + k*144 + seg*16), src + (size_t)k*(size_t)ncols + seg*8);
            }
            const float* rsrc = addsrc + base;
            #pragma unroll
            for (int i = 0; i < 8; i++) {
                int idx = i*256 + tid, k = idx >> 4, seg = idx & 15;
                cp16(sptr(rN + k*272 + seg*16), rsrc + (size_t)k*(size_t)ncols + seg*4);
            }
            CP_COMMIT();
            CP_WAIT1();
        } else {
            CP_WAIT0();
        }
        __syncthreads();

        const char* bS = buf ? bS1 : bS0;
        const char* rS = buf ? rS1 : rS0;
        float acc[2][4][4];
        #pragma unroll
        for (int a = 0; a < 2; a++)
            #pragma unroll
            for (int b = 0; b < 4; b++)
                #pragma unroll
                for (int c = 0; c < 4; c++) acc[a][b][c] = 0.f;

        #pragma unroll
        for (int ks = 0; ks < 8; ks++) {
            #pragma unroll
            for (int nq = 0; nq < 2; nq++) {
                uint32_t b[4];
                ldsm4t(b, sptr(bS + (ks*16 + l15)*144 + (nw*32 + nq*16 + lc8)*2));
                #pragma unroll
                for (int mf = 0; mf < 2; mf++) {
                    mma16(acc[mf][nq*2  ], A[mf][ks].x, A[mf][ks].y, A[mf][ks].z, A[mf][ks].w, b[0], b[1]);
                    mma16(acc[mf][nq*2+1], A[mf][ks].x, A[mf][ks].y, A[mf][ks].z, A[mf][ks].w, b[2], b[3]);
                }
            }
        }

        {
            int bt = t / ntn, nb = t - bt*ntn;
            const size_t base = (size_t)bt*128u*(size_t)ncols + nb*64;
            #pragma unroll
            for (int mf = 0; mf < 2; mf++)
                #pragma unroll
                for (int nf = 0; nf < 4; nf++) {
                    int col = nw*32 + nf*8 + tig*2;
                    #pragma unroll
                    for (int r = 0; r < 2; r++) {
                        int row = mw*32 + mf*16 + g + r*8;
                        float2 rr = *(const float2*)(rS + row*272 + col*4);
                        float2 v;
                        v.x = acc[mf][nf][r*2  ] * scale + rr.x;
                        v.y = acc[mf][nf][r*2+1] * scale + rr.y;
                        *(float2*)&out[base + (size_t)row*(size_t)ncols + col] = v;
                    }
                }
        }
        __syncthreads();
        buf ^= 1;
    }
}

// ---------------------------------------------------------------------------
// fused_h: T = cas@X; MLP (8 chunks of 32 hidden, double-buffered weights);
// softthresh; Z = cas@O2 (smem-transpose epilogue).
// smem: buf 34816 | O1 10240 | Wb1[2] 2*10240 | Wb2[2] 2*8704 = 82944 B.
// FIX vs r13: Wb2 staging = 2 passes x 256 thr (k=idx>>4, seg=idx&15) so all
// 16 segments (256 B) of each of the 32 rows are written.
// ---------------------------------------------------------------------------
__global__ __launch_bounds__(256, 2)
void fused_h(const __half* __restrict__ in, __half* __restrict__ out) {
    char* buf  = (char*)smu;                 // 34816
    char* O1   = buf + 34816;                // 10240
    char* Wb1a = O1 + 10240;                 // 10240
    char* Wb1b = Wb1a + 10240;               // 10240
    char* Wb2a = Wb1b + 10240;               // 8704
    char* Wb2b = Wb2a + 8704;                // 8704

    const int tid  = threadIdx.x;
    const int bI   = blockIdx.x >> 7;
    const int wcol = blockIdx.x & 127;
    const int blk  = blockIdx.y;
    const size_t gbase = ((size_t)(bI*128)*128u + (size_t)wcol)*1024u + (size_t)blk*128u;

    const __half* W1 = g_w1h + blk*BS*HID;
    const __half* W2 = g_w2h + blk*HID*BS;

    // group 0: X tile
    #pragma unroll
    for (int i = 0; i < 8; i++) {
        int idx = i*256 + tid, h = idx >> 4, seg = idx & 15;
        cp16(sptr(buf + h*272 + seg*16), in + gbase + (size_t)h*131072u + seg*8);
    }
    CP_COMMIT();
    // group 1: chunk-0 weights into slot a
    #pragma unroll
    for (int i = 0; i < 2; i++) {           // Wb1: 128k x 32n (64 B/row), 512 cp16
        int idx = i*256 + tid, k = idx >> 2, seg = idx & 3;
        cp16(sptr(Wb1a + k*80 + seg*16), W1 + k*HID + seg*8);
    }
    #pragma unroll
    for (int i = 0; i < 2; i++) {           // Wb2: 32k x 128n (256 B/row), 512 cp16
        int idx = i*256 + tid, k = idx >> 4, seg = idx & 15;
        cp16(sptr(Wb2a + k*272 + seg*16), W2 + (size_t)k*BS + seg*8);
    }
    CP_COMMIT();
    CP_WAIT1();   // X ready; chunk-0 weights still in flight

    const int wid = tid >> 5, lane = tid & 31;
    const int g = lane >> 2, tig = lane & 3;
    const int mw = wid & 3, nw = wid >> 2;
    const int l15 = lane & 15, lc8 = (lane >> 4) * 8;
    const int m0 = mw*32;
    __syncthreads();

    {   // ---- T = cas @ X ----
        float acc[2][8][4];
        #pragma unroll
        for (int a = 0; a < 2; a++) for (int b = 0; b < 8; b++) for (int c = 0; c < 4; c++) acc[a][b][c] = 0.f;
        #pragma unroll
        for (int ks = 0; ks < 8; ks++) {
            uint4 A0 = __ldg(&g_casPH[((mw*2  )*8 + ks)*32 + lane]);
            uint4 A1 = __ldg(&g_casPH[((mw*2+1)*8 + ks)*32 + lane]);
            #pragma unroll
            for (int nq = 0; nq < 4; nq++) {
                uint32_t b[4];
                ldsm4t(b, sptr(buf + (ks*16 + l15)*272 + (nw*64 + nq*16 + lc8)*2));
                mma16(acc[0][nq*2  ], A0.x, A0.y, A0.z, A0.w, b[0], b[1]);
                mma16(acc[0][nq*2+1], A0.x, A0.y, A0.z, A0.w, b[2], b[3]);
                mma16(acc[1][nq*2  ], A1.x, A1.y, A1.z, A1.w, b[0], b[1]);
                mma16(acc[1][nq*2+1], A1.x, A1.y, A1.z, A1.w, b[2], b[3]);
            }
        }
        __syncthreads();
        #pragma unroll
        for (int mf = 0; mf < 2; mf++) for (int nf = 0; nf < 8; nf++) {
            int n = nw*64 + nf*8 + tig*2;
            #pragma unroll
            for (int r = 0; r < 2; r++) {
                int m = m0 + mf*16 + g + r*8;
                *(uint32_t*)(buf + m*272 + n*2) = pack2(acc[mf][nf][r*2], acc[mf][nf][r*2+1]);
            }
        }
        __syncthreads();
    }

    // ---- MLP: 8 chunks of 32 hidden, double-buffered weights ----
    float acc2[2][8][4];
    #pragma unroll
    for (int a = 0; a < 2; a++) for (int b = 0; b < 8; b++) for (int c = 0; c < 4; c++) acc2[a][b][c] = 0.f;

    #pragma unroll 1
    for (int ch = 0; ch < 8; ch++) {
        char* cW1 = (ch & 1) ? Wb1b : Wb1a;
        char* cW2 = (ch & 1) ? Wb2b : Wb2a;
        if (ch < 7) {   // stage next chunk into other slot (overlaps this chunk's GEMMs)
            char* nW1 = (ch & 1) ? Wb1a : Wb1b;
            char* nW2 = (ch & 1) ? Wb2a : Wb2b;
            #pragma unroll
            for (int i = 0; i < 2; i++) {
                int idx = i*256 + tid, k = idx >> 2, seg = idx & 3;
                cp16(sptr(nW1 + k*80 + seg*16), W1 + k*HID + (ch + 1)*32 + seg*8);
            }
            #pragma unroll
            for (int i = 0; i < 2; i++) {
                int idx = i*256 + tid, k = idx >> 4, seg = idx & 15;
                cp16(sptr(nW2 + k*272 + seg*16), W2 + (size_t)((ch + 1)*32 + k)*BS + seg*8);
            }
            CP_COMMIT();
            CP_WAIT1();   // current chunk complete, next in flight
        } else {
            CP_WAIT0();
        }
        __syncthreads();

        // GEMM1: [128,128]@[128,32]; warp n-range 16
        float acc1[2][2][4];
        #pragma unroll
        for (int a = 0; a < 2; a++) for (int b = 0; b < 2; b++) for (int c = 0; c < 4; c++) acc1[a][b][c] = 0.f;

        #pragma unroll
        for (int ks = 0; ks < 8; ks++) {
            uint32_t a0[4], a1[4], b[4];
            ldsm4(a0, sptr(buf + (m0      + l15)*272 + (ks*16 + lc8)*2));
            ldsm4(a1, sptr(buf + (m0 + 16 + l15)*272 + (ks*16 + lc8)*2));
            ldsm4t(b, sptr(cW1 + (ks*16 + l15)*80 + (nw*16 + lc8)*2));
            mma16(acc1[0][0], a0[0], a0[1], a0[2], a0[3], b[0], b[1]);
            mma16(acc1[0][1], a0[0], a0[1], a0[2], a0[3], b[2], b[3]);
            mma16(acc1[1][0], a1[0], a1[1], a1[2], a1[3], b[0], b[1]);
            mma16(acc1[1][1], a1[0], a1[1], a1[2], a1[3], b[2], b[3]);
        }

        // bias + relu -> O1 [128][32] pitch 80
        #pragma unroll
        for (int mf = 0; mf < 2; mf++) for (int nf = 0; nf < 2; nf++) {
            int nc = nw*16 + nf*8 + tig*2;
            float bx = g_b1s[blk*HID + ch*32 + nc];
            float by = g_b1s[blk*HID + ch*32 + nc + 1];
            #pragma unroll
            for (int r = 0; r < 2; r++) {
                int m = m0 + mf*16 + g + r*8;
                *(uint32_t*)(O1 + m*80 + nc*2) =
                    pack2(fmaxf(acc1[mf][nf][r*2] + bx, 0.f), fmaxf(acc1[mf][nf][r*2+1] + by, 0.f));
            }
        }
        __syncthreads();   // O1 complete (cross-warp columns)

        // GEMM2 partial: [128,32]@[32,128]; 2 ksteps
        #pragma unroll
        for (int ks = 0; ks < 2; ks++) {
            uint32_t a0[4], a1[4];
            ldsm4(a0, sptr(O1 + (m0      + l15)*80 + (ks*16 + lc8)*2));
            ldsm4(a1, sptr(O1 + (m0 + 16 + l15)*80 + (ks*16 + lc8)*2));
            #pragma unroll
            for (int nq = 0; nq < 4; nq++) {
                uint32_t b[4];
                ldsm4t(b, sptr(cW2 + (ks*16 + l15)*272 + (nw*64 + nq*16 + lc8)*2));
                mma16(acc2[0][nq*2  ], a0[0], a0[1], a0[2], a0[3], b[0], b[1]);
                mma16(acc2[0][nq*2+1], a0[0], a0[1], a0[2], a0[3], b[2], b[3]);
                mma16(acc2[1][nq*2  ], a1[0], a1[1], a1[2], a1[3], b[0], b[1]);
                mma16(acc2[1][nq*2+1], a1[0], a1[1], a1[2], a1[3], b[2], b[3]);
            }
        }
        __syncthreads();   // O1/current-slot reads done before restage next iter
    }

    // ---- O2 = softthresh(acc2 + b2) -> buf ----
    #pragma unroll
    for (int mf = 0; mf < 2; mf++) for (int nf = 0; nf < 8; nf++) {
        int n = nw*64 + nf*8 + tig*2;
        float bx = g_b2s[blk*BS + n], by = g_b2s[blk*BS + n + 1];
        #pragma unroll
        for (int r = 0; r < 2; r++) {
            int m = m0 + mf*16 + g + r*8;
            *(uint32_t*)(buf + m*272 + n*2) =
                pack2(sthr(acc2[mf][nf][r*2] + bx), sthr(acc2[mf][nf][r*2+1] + by));
        }
    }
    __syncthreads();

    {   // ---- Z = cas @ O2 ----
        float acc[2][8][4];
        #pragma unroll
        for (int a = 0; a < 2; a++) for (int b = 0; b < 8; b++) for (int c = 0; c < 4; c++) acc[a][b][c] = 0.f;
        #pragma unroll
        for (int ks = 0; ks < 8; ks++) {
            uint4 A0 = __ldg(&g_casPH[((mw*2  )*8 + ks)*32 + lane]);
            uint4 A1 = __ldg(&g_casPH[((mw*2+1)*8 + ks)*32 + lane]);
            #pragma unroll
            for (int nq = 0; nq < 4; nq++) {
                uint32_t b[4];
                ldsm4t(b, sptr(buf + (ks*16 + l15)*272 + (nw*64 + nq*16 + lc8)*2));
                mma16(acc[0][nq*2  ], A0.x, A0.y, A0.z, A0.w, b[0], b[1]);
                mma16(acc[0][nq*2+1], A0.x, A0.y, A0.z, A0.w, b[2], b[3]);
                mma16(acc[1][nq*2  ], A1.x, A1.y, A1.z, A1.w, b[0], b[1]);
                mma16(acc[1][nq*2+1], A1.x, A1.y, A1.z, A1.w, b[2], b[3]);
            }
        }

        __syncthreads();   // all Z reads of buf done -> reuse buf as scratch (pitch 256B)
        #pragma unroll
        for (int mf = 0; mf < 2; mf++) for (int nf = 0; nf < 8; nf++) {
            #pragma unroll
            for (int r = 0; r < 2; r++) {
                int m = m0 + mf*16 + g + r*8;   // m&7 == g
                *(uint32_t*)(buf + m*256 + (((nw << 3) | (nf ^ g)) << 4) + tig*4) =
                    pack2(acc[mf][nf][r*2], acc[mf][nf][r*2+1]);
            }
        }
        __syncthreads();
        #pragma unroll
        for (int pass = 0; pass < 8; pass++) {
            int row = pass*16 + (tid >> 4);
            int q = tid & 15;
            int ch = (q & 8) | ((q & 7) ^ (row & 7));
            uint4 v = *(uint4*)(buf + row*256 + ch*16);
            *(uint4*)(out + gbase + (size_t)row*131072u + q*8) = v;
        }
    }
}

// ---------------------------------------------------------------------------
extern "C" void kernel_launch(void* const* d_in, const int* in_sizes, int n_in,
                              void* d_out, int out_size) {
    const float* x  = (const float*)d_in[0];
    const float* w1 = (const float*)d_in[1];
    const float* b1 = (const float*)d_in[2];
    const float* w2 = (const float*)d_in[3];
    const float* b2 = (const float*)d_in[4];
    float* out = (float*)d_out;

    void *p1, *p2;
    cudaGetSymbolAddress(&p1, g_bh1);
    cudaGetSymbolAddress(&p2, g_bh2);
    __half* bh1 = (__half*)p1;
    __half* bh2 = (__half*)p2;

    const int CAS1_SMEM = 18432;
    const int CAS2_SMEM = 2*18432 + 2*34816;                // 106496
    const int MID_SMEM  = 34816 + 10240 + 2*10240 + 2*8704; // 82944
    cudaFuncSetAttribute(casmul_f2h, cudaFuncAttributeMaxDynamicSharedMemorySize, CAS1_SMEM);
    cudaFuncSetAttribute(casmul_h2f, cudaFuncAttributeMaxDynamicSharedMemorySize, CAS2_SMEM);
    cudaFuncSetAttribute(fused_h,    cudaFuncAttributeMaxDynamicSharedMemorySize, MID_SMEM);

    prep_kernel<<<1024, 256>>>(w1, b1, w2, b2);

    const int GRID = 296;
    const int T1 = (CC/64) * (BB*HH);      // 8192 tiles

    casmul_f2h<<<GRID, 256, CAS1_SMEM>>>(x, bh1, CC, T1);
    fused_h<<<dim3(BB*WW, NB), 256, MID_SMEM>>>(bh1, bh2);
    casmul_h2f<<<GRID, 256, CAS2_SMEM>>>(bh2, out, x, 1.0f/(HH*WW), CC, T1);
}

// round 16
// speedup vs baseline: 1.0290x; 1.0290x over previous
#include <cuda_runtime.h>
#include <cuda_fp16.h>
#include <stdint.h>

#define BB 4
#define HH 128
#define WW 128
#define CC 1024
#define NB 8
#define BS 128
#define HID 256
#define LAM 0.01f
#define NTOT (BB*HH*WW*CC)

__device__ __align__(128) __half g_bh1[NTOT];
__device__ __align__(128) __half g_bh2[NTOT];
__device__ __align__(16) uint4 g_casPH[8*8*32];   // m16n8k16 A-fragment layout
__device__ __align__(16) __half g_w1h[NB*BS*HID];
__device__ __align__(16) __half g_w2h[NB*HID*BS];
__device__ float g_b1s[NB*HID];
__device__ float g_b2s[NB*BS];

// ---------------- helpers ----------------
__device__ __forceinline__ void mma16(float* c, uint32_t a0, uint32_t a1, uint32_t a2, uint32_t a3,
                                      uint32_t b0, uint32_t b1) {
    asm volatile("mma.sync.aligned.m16n8k16.row.col.f32.f16.f16.f32 "
                 "{%0,%1,%2,%3}, {%4,%5,%6,%7}, {%8,%9}, {%0,%1,%2,%3};"
                 : "+f"(c[0]), "+f"(c[1]), "+f"(c[2]), "+f"(c[3])
                 : "r"(a0), "r"(a1), "r"(a2), "r"(a3), "r"(b0), "r"(b1));
}
__device__ __forceinline__ void ldsm4(uint32_t* r, uint32_t a) {
    asm volatile("ldmatrix.sync.aligned.m8n8.x4.shared.b16 {%0,%1,%2,%3}, [%4];"
                 : "=r"(r[0]), "=r"(r[1]), "=r"(r[2]), "=r"(r[3]) : "r"(a));
}
__device__ __forceinline__ void ldsm4t(uint32_t* r, uint32_t a) {
    asm volatile("ldmatrix.sync.aligned.m8n8.x4.trans.shared.b16 {%0,%1,%2,%3}, [%4];"
                 : "=r"(r[0]), "=r"(r[1]), "=r"(r[2]), "=r"(r[3]) : "r"(a));
}
__device__ __forceinline__ void cp16(uint32_t saddr, const void* gptr) {
    asm volatile("cp.async.cg.shared.global [%0], [%1], 16;" :: "r"(saddr), "l"(gptr));
}
#define CP_COMMIT() asm volatile("cp.async.commit_group;")
#define CP_WAIT2()  asm volatile("cp.async.wait_group 2;" ::: "memory")
#define CP_WAIT1()  asm volatile("cp.async.wait_group 1;" ::: "memory")
#define CP_WAIT0()  asm volatile("cp.async.wait_group 0;" ::: "memory")
__device__ __forceinline__ uint32_t sptr(const void* p) {
    return (uint32_t)__cvta_generic_to_shared(p);
}
__device__ __forceinline__ uint32_t pack2(float a, float b) {
    __half2 h = __floats2half2_rn(a, b);
    return *reinterpret_cast<uint32_t*>(&h);
}
__device__ __forceinline__ float sthr(float z) {
    return (z > LAM) ? (z - LAM) : ((z < -LAM) ? (z + LAM) : 0.f);
}

// ---------------- prep ----------------
__device__ __forceinline__ float casv(int m, int k) {
    float s, c;
    sincospif((float)((m*k) & 127) * (1.0f/64.0f), &s, &c);
    return c + s;
}
__global__ void prep_kernel(const float* __restrict__ w1, const float* __restrict__ b1,
                            const float* __restrict__ w2, const float* __restrict__ b2) {
    int t = blockIdx.x * blockDim.x + threadIdx.x;
    if (t < 8*8*32) {
        int lane = t & 31, ks = (t >> 5) & 7, mt = t >> 8;
        int g = lane >> 2, tig = lane & 3;
        int m0 = mt*16 + g, k0 = ks*16 + 2*tig;
        uint4 v;
        v.x = pack2(casv(m0, k0),     casv(m0, k0+1));
        v.y = pack2(casv(m0+8, k0),   casv(m0+8, k0+1));
        v.z = pack2(casv(m0, k0+8),   casv(m0, k0+9));
        v.w = pack2(casv(m0+8, k0+8), casv(m0+8, k0+9));
        g_casPH[t] = v;
    }
    if (t < NB*BS*HID) {
        g_w1h[t] = __float2half(w1[t] + w1[NB*BS*HID + t]);
        g_w2h[t] = __float2half(w2[t] + w2[NB*HID*BS + t]);
    }
    if (t < NB*HID) g_b1s[t] = b1[t];
    if (t < NB*BS)  g_b2s[t] = b2[t];
}

extern __shared__ uint32_t smu[];

// ---------------------------------------------------------------------------
// casmul_f2h: pass 1 (validated). OUT_h = cas @ IN_f. smem = 18432 B.
// ---------------------------------------------------------------------------
__global__ __launch_bounds__(256, 2)
void casmul_f2h(const float* __restrict__ in, __half* __restrict__ out,
                int ncols, int total) {
    char* bS = (char*)smu;
    const int tid = threadIdx.x;
    const int w = tid >> 5, lane = tid & 31;
    const int g = lane >> 2, tig = lane & 3;
    const int l15 = lane & 15, lc8 = (lane >> 4) * 8;
    const int ntn = ncols >> 6;

    uint4 A[8];
    #pragma unroll
    for (int ks = 0; ks < 8; ks++)
        A[ks] = __ldg(&g_casPH[(w*8 + ks)*32 + lane]);

    float4 pf[8];
    int t = blockIdx.x;
    {
        int bt = t / ntn, nb = t - bt*ntn;
        const float* src = in + (size_t)bt*128u*(size_t)ncols + nb*64;
        #pragma unroll
        for (int i = 0; i < 8; i++) {
            int idx = i*256 + tid, k = idx >> 4, n4 = (idx & 15) << 2;
            pf[i] = *(const float4*)(src + (size_t)k*(size_t)ncols + n4);
        }
    }

    for (; t < total; t += gridDim.x) {
        __syncthreads();
        #pragma unroll
        for (int i = 0; i < 8; i++) {
            int idx = i*256 + tid, k = idx >> 4, n4 = (idx & 15) << 2;
            uint2 u;
            u.x = pack2(pf[i].x, pf[i].y);
            u.y = pack2(pf[i].z, pf[i].w);
            *(uint2*)(bS + k*144 + n4*2) = u;
        }
        __syncthreads();

        int tn = t + gridDim.x;
        if (tn < total) {
            int bt = tn / ntn, nb = tn - bt*ntn;
            const float* src = in + (size_t)bt*128u*(size_t)ncols + nb*64;
            #pragma unroll
            for (int i = 0; i < 8; i++) {
                int idx = i*256 + tid, k = idx >> 4, n4 = (idx & 15) << 2;
                pf[i] = *(const float4*)(src + (size_t)k*(size_t)ncols + n4);
            }
        }

        float acc[8][4];
        #pragma unroll
        for (int i = 0; i < 8; i++)
            #pragma unroll
            for (int j = 0; j < 4; j++) acc[i][j] = 0.f;

        #pragma unroll
        for (int ks = 0; ks < 8; ks++) {
            #pragma unroll
            for (int nq = 0; nq < 4; nq++) {
                uint32_t b[4];
                ldsm4t(b, sptr(bS + (ks*16 + l15)*144 + (nq*16 + lc8)*2));
                mma16(acc[nq*2  ], A[ks].x, A[ks].y, A[ks].z, A[ks].w, b[0], b[1]);
                mma16(acc[nq*2+1], A[ks].x, A[ks].y, A[ks].z, A[ks].w, b[2], b[3]);
            }
        }

        __syncthreads();
        #pragma unroll
        for (int nf = 0; nf < 8; nf++)
            #pragma unroll
            for (int r = 0; r < 2; r++) {
                int row = w*16 + g + r*8;
                *(uint32_t*)(bS + row*128 + ((nf ^ g) << 4) + tig*4) =
                    pack2(acc[nf][r*2], acc[nf][r*2+1]);
            }
        __syncwarp();
        {
            int bt = t / ntn, nb = t - bt*ntn;
            const size_t base = (size_t)bt*128u*(size_t)ncols + nb*64;
            #pragma unroll
            for (int i = 0; i < 4; i++) {
                int row = w*16 + (lane >> 3) + i*4;
                int q = lane & 7;
                uint4 v = *(uint4*)(bS + row*128 + ((q ^ (row & 7)) << 4));
                *(uint4*)(out + base + (size_t)row*(size_t)ncols + q*8) = v;
            }
        }
    }
}

// ---------------------------------------------------------------------------
// casmul_h2f: pass 5 (validated). OUT_f = scale*(cas @ IN_h) + add_f.
// B + residual cp.async double-buffered. smem = 106496 B.
// ---------------------------------------------------------------------------
__global__ __launch_bounds__(256, 2)
void casmul_h2f(const __half* __restrict__ in, float* __restrict__ out,
                const float* __restrict__ addsrc, float scale, int ncols, int total) {
    char* bS0 = (char*)smu;
    char* bS1 = bS0 + 18432;
    char* rS0 = bS1 + 18432;
    char* rS1 = rS0 + 34816;
    const int tid = threadIdx.x;
    const int w = tid >> 5, lane = tid & 31;
    const int g = lane >> 2, tig = lane & 3;
    const int l15 = lane & 15, lc8 = (lane >> 4) * 8;
    const int mw = w & 3, nw = w >> 2;
    const int ntn = ncols >> 6;

    uint4 A[2][8];
    #pragma unroll
    for (int mf = 0; mf < 2; mf++)
        #pragma unroll
        for (int ks = 0; ks < 8; ks++)
            A[mf][ks] = __ldg(&g_casPH[((mw*2 + mf)*8 + ks)*32 + lane]);

    int t = blockIdx.x;
    {
        int bt = t / ntn, nb = t - bt*ntn;
        const size_t base = (size_t)bt*128u*(size_t)ncols + nb*64;
        const __half* src = in + base;
        #pragma unroll
        for (int i = 0; i < 4; i++) {
            int idx = i*256 + tid, k = idx >> 3, seg = idx & 7;
            cp16(sptr(bS0 + k*144 + seg*16), src + (size_t)k*(size_t)ncols + seg*8);
        }
        const float* rsrc = addsrc + base;
        #pragma unroll
        for (int i = 0; i < 8; i++) {
            int idx = i*256 + tid, k = idx >> 4, seg = idx & 15;
            cp16(sptr(rS0 + k*272 + seg*16), rsrc + (size_t)k*(size_t)ncols + seg*4);
        }
        CP_COMMIT();
    }

    int buf = 0;
    for (; t < total; t += gridDim.x) {
        int tn = t + gridDim.x;
        if (tn < total) {
            char* bN = buf ? bS0 : bS1;
            char* rN = buf ? rS0 : rS1;
            int bt = tn / ntn, nb = tn - bt*ntn;
            const size_t base = (size_t)bt*128u*(size_t)ncols + nb*64;
            const __half* src = in + base;
            #pragma unroll
            for (int i = 0; i < 4; i++) {
                int idx = i*256 + tid, k = idx >> 3, seg = idx & 7;
                cp16(sptr(bN + k*144 + seg*16), src + (size_t)k*(size_t)ncols + seg*8);
            }
            const float* rsrc = addsrc + base;
            #pragma unroll
            for (int i = 0; i < 8; i++) {
                int idx = i*256 + tid, k = idx >> 4, seg = idx & 15;
                cp16(sptr(rN + k*272 + seg*16), rsrc + (size_t)k*(size_t)ncols + seg*4);
            }
            CP_COMMIT();
            CP_WAIT1();
        } else {
            CP_WAIT0();
        }
        __syncthreads();

        const char* bS = buf ? bS1 : bS0;
        const char* rS = buf ? rS1 : rS0;
        float acc[2][4][4];
        #pragma unroll
        for (int a = 0; a < 2; a++)
            #pragma unroll
            for (int b = 0; b < 4; b++)
                #pragma unroll
                for (int c = 0; c < 4; c++) acc[a][b][c] = 0.f;

        #pragma unroll
        for (int ks = 0; ks < 8; ks++) {
            #pragma unroll
            for (int nq = 0; nq < 2; nq++) {
                uint32_t b[4];
                ldsm4t(b, sptr(bS + (ks*16 + l15)*144 + (nw*32 + nq*16 + lc8)*2));
                #pragma unroll
                for (int mf = 0; mf < 2; mf++) {
                    mma16(acc[mf][nq*2  ], A[mf][ks].x, A[mf][ks].y, A[mf][ks].z, A[mf][ks].w, b[0], b[1]);
                    mma16(acc[mf][nq*2+1], A[mf][ks].x, A[mf][ks].y, A[mf][ks].z, A[mf][ks].w, b[2], b[3]);
                }
            }
        }

        {
            int bt = t / ntn, nb = t - bt*ntn;
            const size_t base = (size_t)bt*128u*(size_t)ncols + nb*64;
            #pragma unroll
            for (int mf = 0; mf < 2; mf++)
                #pragma unroll
                for (int nf = 0; nf < 4; nf++) {
                    int col = nw*32 + nf*8 + tig*2;
                    #pragma unroll
                    for (int r = 0; r < 2; r++) {
                        int row = mw*32 + mf*16 + g + r*8;
                        float2 rr = *(const float2*)(rS + row*272 + col*4);
                        float2 v;
                        v.x = acc[mf][nf][r*2  ] * scale + rr.x;
                        v.y = acc[mf][nf][r*2+1] * scale + rr.y;
                        *(float2*)&out[base + (size_t)row*(size_t)ncols + col] = v;
                    }
                }
        }
        __syncthreads();
        buf ^= 1;
    }
}

// ---------------------------------------------------------------------------
// fused_h: round-12 structure (4 chunks of 64 hidden) + software-pipelined
// weight staging: Wb1 restaged during GEMM2(ch), Wb2 restaged during
// GEMM1(ch+1). Same smem (89088 B, 2 CTAs/SM), same accumulation order.
// Prologue: 3 cp groups (X / W1[0] / W2[0]) so T-phase hides weight fetch.
// ---------------------------------------------------------------------------
__global__ __launch_bounds__(256, 2)
void fused_h(const __half* __restrict__ in, __half* __restrict__ out) {
    char* buf = (char*)smu;                  // 34816
    char* O1  = buf + 34816;                 // 18432
    char* Wb1 = O1 + 18432;                  // 18432
    char* Wb2 = Wb1 + 18432;                 // 17408

    const int tid  = threadIdx.x;
    const int bI   = blockIdx.x >> 7;
    const int wcol = blockIdx.x & 127;
    const int blk  = blockIdx.y;
    const size_t gbase = ((size_t)(bI*128)*128u + (size_t)wcol)*1024u + (size_t)blk*128u;

    const __half* W1 = g_w1h + blk*BS*HID;
    const __half* W2 = g_w2h + blk*HID*BS;

    // group 0: X tile
    #pragma unroll
    for (int i = 0; i < 8; i++) {
        int idx = i*256 + tid, h = idx >> 4, seg = idx & 15;
        cp16(sptr(buf + h*272 + seg*16), in + gbase + (size_t)h*131072u + seg*8);
    }
    CP_COMMIT();
    // group 1: W1 chunk 0 [128k][64n] pitch 144
    #pragma unroll
    for (int i = 0; i < 4; i++) {
        int idx = i*256 + tid, k = idx >> 3, seg = idx & 7;
        cp16(sptr(Wb1 + k*144 + seg*16), W1 + k*HID + seg*8);
    }
    CP_COMMIT();
    // group 2: W2 chunk 0 [64k][128n] pitch 272
    #pragma unroll
    for (int i = 0; i < 4; i++) {
        int idx = i*256 + tid, k = idx >> 4, seg = idx & 15;
        cp16(sptr(Wb2 + k*272 + seg*16), W2 + (size_t)k*BS + seg*8);
    }
    CP_COMMIT();
    CP_WAIT2();   // X done; W1[0]/W2[0] in flight under T-phase

    const int wid = tid >> 5, lane = tid & 31;
    const int g = lane >> 2, tig = lane & 3;
    const int mw = wid & 3, nw = wid >> 2;
    const int l15 = lane & 15, lc8 = (lane >> 4) * 8;
    const int m0 = mw*32;
    __syncthreads();

    {   // ---- T = cas @ X ----
        float acc[2][8][4];
        #pragma unroll
        for (int a = 0; a < 2; a++) for (int b = 0; b < 8; b++) for (int c = 0; c < 4; c++) acc[a][b][c] = 0.f;
        #pragma unroll
        for (int ks = 0; ks < 8; ks++) {
            uint4 A0 = __ldg(&g_casPH[((mw*2  )*8 + ks)*32 + lane]);
            uint4 A1 = __ldg(&g_casPH[((mw*2+1)*8 + ks)*32 + lane]);
            #pragma unroll
            for (int nq = 0; nq < 4; nq++) {
                uint32_t b[4];
                ldsm4t(b, sptr(buf + (ks*16 + l15)*272 + (nw*64 + nq*16 + lc8)*2));
                mma16(acc[0][nq*2  ], A0.x, A0.y, A0.z, A0.w, b[0], b[1]);
                mma16(acc[0][nq*2+1], A0.x, A0.y, A0.z, A0.w, b[2], b[3]);
                mma16(acc[1][nq*2  ], A1.x, A1.y, A1.z, A1.w, b[0], b[1]);
                mma16(acc[1][nq*2+1], A1.x, A1.y, A1.z, A1.w, b[2], b[3]);
            }
        }
        __syncthreads();
        #pragma unroll
        for (int mf = 0; mf < 2; mf++) for (int nf = 0; nf < 8; nf++) {
            int n = nw*64 + nf*8 + tig*2;
            #pragma unroll
            for (int r = 0; r < 2; r++) {
                int m = m0 + mf*16 + g + r*8;
                *(uint32_t*)(buf + m*272 + n*2) = pack2(acc[mf][nf][r*2], acc[mf][nf][r*2+1]);
            }
        }
        __syncthreads();
    }

    // ---- MLP: 4 chunks of 64 hidden, pipelined weight staging ----
    float acc2[2][8][4];
    #pragma unroll
    for (int a = 0; a < 2; a++) for (int b = 0; b < 8; b++) for (int c = 0; c < 4; c++) acc2[a][b][c] = 0.f;

    #pragma unroll 1
    for (int ch = 0; ch < 4; ch++) {
        // entering: oldest pending group = W1[ch]; next = W2[ch]
        CP_WAIT1();        // W1[ch] landed (W2[ch] may still be in flight)
        __syncthreads();

        // ---- GEMM1: [128,128]@[128,64], warp n-range 32 ----
        float acc1[2][4][4];
        #pragma unroll
        for (int a = 0; a < 2; a++) for (int b = 0; b < 4; b++) for (int c = 0; c < 4; c++) acc1[a][b][c] = 0.f;

        #pragma unroll
        for (int ks = 0; ks < 8; ks++) {
            uint32_t a0[4], a1[4];
            ldsm4(a0, sptr(buf + (m0      + l15)*272 + (ks*16 + lc8)*2));
            ldsm4(a1, sptr(buf + (m0 + 16 + l15)*272 + (ks*16 + lc8)*2));
            #pragma unroll
            for (int nq = 0; nq < 2; nq++) {
                uint32_t b[4];
                ldsm4t(b, sptr(Wb1 + (ks*16 + l15)*144 + (nw*32 + nq*16 + lc8)*2));
                mma16(acc1[0][nq*2  ], a0[0], a0[1], a0[2], a0[3], b[0], b[1]);
                mma16(acc1[0][nq*2+1], a0[0], a0[1], a0[2], a0[3], b[2], b[3]);
                mma16(acc1[1][nq*2  ], a1[0], a1[1], a1[2], a1[3], b[0], b[1]);
                mma16(acc1[1][nq*2+1], a1[0], a1[1], a1[2], a1[3], b[2], b[3]);
            }
        }

        // bias + relu -> O1 [128][64] pitch 144
        #pragma unroll
        for (int mf = 0; mf < 2; mf++) for (int nf = 0; nf < 4; nf++) {
            int nc = nw*32 + nf*8 + tig*2;
            float bx = g_b1s[blk*HID + ch*64 + nc];
            float by = g_b1s[blk*HID + ch*64 + nc + 1];
            #pragma unroll
            for (int r = 0; r < 2; r++) {
                int m = m0 + mf*16 + g + r*8;
                *(uint32_t*)(O1 + m*144 + nc*2) =
                    pack2(fmaxf(acc1[mf][nf][r*2] + bx, 0.f), fmaxf(acc1[mf][nf][r*2+1] + by, 0.f));
            }
        }
        __syncthreads();   // O1 complete; Wb1 free (all GEMM1 reads done)

        // restage Wb1 <- W1[ch+1] (lands during GEMM2)
        if (ch < 3) {
            #pragma unroll
            for (int i = 0; i < 4; i++) {
                int idx = i*256 + tid, k = idx >> 3, seg = idx & 7;
                cp16(sptr(Wb1 + k*144 + seg*16), W1 + k*HID + (ch + 1)*64 + seg*8);
            }
            CP_COMMIT();
            CP_WAIT1();    // W2[ch] landed (new W1 group in flight)
        } else {
            CP_WAIT0();    // W2[3] landed
        }
        __syncthreads();

        // ---- GEMM2 partial: [128,64]@[64,128], warp n-range 64 ----
        #pragma unroll
        for (int ks = 0; ks < 4; ks++) {
            uint32_t a0[4], a1[4];
            ldsm4(a0, sptr(O1 + (m0      + l15)*144 + (ks*16 + lc8)*2));
            ldsm4(a1, sptr(O1 + (m0 + 16 + l15)*144 + (ks*16 + lc8)*2));
            #pragma unroll
            for (int nq = 0; nq < 4; nq++) {
                uint32_t b[4];
                ldsm4t(b, sptr(Wb2 + (ks*16 + l15)*272 + (nw*64 + nq*16 + lc8)*2));
                mma16(acc2[0][nq*2  ], a0[0], a0[1], a0[2], a0[3], b[0], b[1]);
                mma16(acc2[0][nq*2+1], a0[0], a0[1], a0[2], a0[3], b[2], b[3]);
                mma16(acc2[1][nq*2  ], a1[0], a1[1], a1[2], a1[3], b[0], b[1]);
                mma16(acc2[1][nq*2+1], a1[0], a1[1], a1[2], a1[3], b[2], b[3]);
            }
        }
        __syncthreads();   // Wb2 + O1 free (all GEMM2 reads done)

        // restage Wb2 <- W2[ch+1] (lands during next GEMM1)
        if (ch < 3) {
            #pragma unroll
            for (int i = 0; i < 4; i++) {
                int idx = i*256 + tid, k = idx >> 4, seg = idx & 15;
                cp16(sptr(Wb2 + k*272 + seg*16), W2 + (size_t)((ch + 1)*64 + k)*BS + seg*8);
            }
            CP_COMMIT();
        }
    }

    // ---- O2 = softthresh(acc2 + b2) -> buf ----
    #pragma unroll
    for (int mf = 0; mf < 2; mf++) for (int nf = 0; nf < 8; nf++) {
        int n = nw*64 + nf*8 + tig*2;
        float bx = g_b2s[blk*BS + n], by = g_b2s[blk*BS + n + 1];
        #pragma unroll
        for (int r = 0; r < 2; r++) {
            int m = m0 + mf*16 + g + r*8;
            *(uint32_t*)(buf + m*272 + n*2) =
                pack2(sthr(acc2[mf][nf][r*2] + bx), sthr(acc2[mf][nf][r*2+1] + by));
        }
    }
    __syncthreads();

    {   // ---- Z = cas @ O2 ----
        float acc[2][8][4];
        #pragma unroll
        for (int a = 0; a < 2; a++) for (int b = 0; b < 8; b++) for (int c = 0; c < 4; c++) acc[a][b][c] = 0.f;
        #pragma unroll
        for (int ks = 0; ks < 8; ks++) {
            uint4 A0 = __ldg(&g_casPH[((mw*2  )*8 + ks)*32 + lane]);
            uint4 A1 = __ldg(&g_casPH[((mw*2+1)*8 + ks)*32 + lane]);
            #pragma unroll
            for (int nq = 0; nq < 4; nq++) {
                uint32_t b[4];
                ldsm4t(b, sptr(buf + (ks*16 + l15)*272 + (nw*64 + nq*16 + lc8)*2));
                mma16(acc[0][nq*2  ], A0.x, A0.y, A0.z, A0.w, b[0], b[1]);
                mma16(acc[0][nq*2+1], A0.x, A0.y, A0.z, A0.w, b[2], b[3]);
                mma16(acc[1][nq*2  ], A1.x, A1.y, A1.z, A1.w, b[0], b[1]);
                mma16(acc[1][nq*2+1], A1.x, A1.y, A1.z, A1.w, b[2], b[3]);
            }
        }

        __syncthreads();   // all Z reads of buf done -> reuse buf as scratch (pitch 256B)
        #pragma unroll
        for (int mf = 0; mf < 2; mf++) for (int nf = 0; nf < 8; nf++) {
            #pragma unroll
            for (int r = 0; r < 2; r++) {
                int m = m0 + mf*16 + g + r*8;   // m&7 == g
                *(uint32_t*)(buf + m*256 + (((nw << 3) | (nf ^ g)) << 4) + tig*4) =
                    pack2(acc[mf][nf][r*2], acc[mf][nf][r*2+1]);
            }
        }
        __syncthreads();
        #pragma unroll
        for (int pass = 0; pass < 8; pass++) {
            int row = pass*16 + (tid >> 4);
            int q = tid & 15;
            int ch = (q & 8) | ((q & 7) ^ (row & 7));
            uint4 v = *(uint4*)(buf + row*256 + ch*16);
            *(uint4*)(out + gbase + (size_t)row*131072u + q*8) = v;
        }
    }
}

// ---------------------------------------------------------------------------
extern "C" void kernel_launch(void* const* d_in, const int* in_sizes, int n_in,
                              void* d_out, int out_size) {
    const float* x  = (const float*)d_in[0];
    const float* w1 = (const float*)d_in[1];
    const float* b1 = (const float*)d_in[2];
    const float* w2 = (const float*)d_in[3];
    const float* b2 = (const float*)d_in[4];
    float* out = (float*)d_out;

    void *p1, *p2;
    cudaGetSymbolAddress(&p1, g_bh1);
    cudaGetSymbolAddress(&p2, g_bh2);
    __half* bh1 = (__half*)p1;
    __half* bh2 = (__half*)p2;

    const int CAS1_SMEM = 18432;
    const int CAS2_SMEM = 2*18432 + 2*34816;               // 106496
    const int MID_SMEM  = 34816 + 18432 + 18432 + 17408;   // 89088
    cudaFuncSetAttribute(casmul_f2h, cudaFuncAttributeMaxDynamicSharedMemorySize, CAS1_SMEM);
    cudaFuncSetAttribute(casmul_h2f, cudaFuncAttributeMaxDynamicSharedMemorySize, CAS2_SMEM);
    cudaFuncSetAttribute(fused_h,    cudaFuncAttributeMaxDynamicSharedMemorySize, MID_SMEM);

    prep_kernel<<<1024, 256>>>(w1, b1, w2, b2);

    const int GRID = 296;
    const int T1 = (CC/64) * (BB*HH);      // 8192 tiles

    casmul_f2h<<<GRID, 256, CAS1_SMEM>>>(x, bh1, CC, T1);
    fused_h<<<dim3(BB*WW, NB), 256, MID_SMEM>>>(bh1, bh2);
    casmul_h2f<<<GRID, 256, CAS2_SMEM>>>(bh2, out, x, 1.0f/(HH*WW), CC, T1);
}

// round 17
// speedup vs baseline: 1.0633x; 1.0334x over previous
#include <cuda_runtime.h>
#include <cuda_fp16.h>
#include <stdint.h>

#define BB 4
#define HH 128
#define WW 128
#define CC 1024
#define NB 8
#define BS 128
#define HID 256
#define LAM 0.01f
#define NTOT (BB*HH*WW*CC)

__device__ __align__(128) __half g_bh1[NTOT];
__device__ __align__(128) __half g_bh2[NTOT];
__device__ __align__(16) uint4 g_casPH[8*8*32];   // m16n8k16 A-fragment layout
__device__ __align__(16) __half g_w1h[NB*BS*HID];
__device__ __align__(16) __half g_w2h[NB*HID*BS];
__device__ float g_b1s[NB*HID];
__device__ float g_b2s[NB*BS];

// ---------------- helpers ----------------
__device__ __forceinline__ void mma16(float* c, uint32_t a0, uint32_t a1, uint32_t a2, uint32_t a3,
                                      uint32_t b0, uint32_t b1) {
    asm volatile("mma.sync.aligned.m16n8k16.row.col.f32.f16.f16.f32 "
                 "{%0,%1,%2,%3}, {%4,%5,%6,%7}, {%8,%9}, {%0,%1,%2,%3};"
                 : "+f"(c[0]), "+f"(c[1]), "+f"(c[2]), "+f"(c[3])
                 : "r"(a0), "r"(a1), "r"(a2), "r"(a3), "r"(b0), "r"(b1));
}
__device__ __forceinline__ void ldsm4(uint32_t* r, uint32_t a) {
    asm volatile("ldmatrix.sync.aligned.m8n8.x4.shared.b16 {%0,%1,%2,%3}, [%4];"
                 : "=r"(r[0]), "=r"(r[1]), "=r"(r[2]), "=r"(r[3]) : "r"(a));
}
__device__ __forceinline__ void ldsm4t(uint32_t* r, uint32_t a) {
    asm volatile("ldmatrix.sync.aligned.m8n8.x4.trans.shared.b16 {%0,%1,%2,%3}, [%4];"
                 : "=r"(r[0]), "=r"(r[1]), "=r"(r[2]), "=r"(r[3]) : "r"(a));
}
__device__ __forceinline__ void cp16(uint32_t saddr, const void* gptr) {
    asm volatile("cp.async.cg.shared.global [%0], [%1], 16;" :: "r"(saddr), "l"(gptr));
}
#define CP_COMMIT() asm volatile("cp.async.commit_group;")
#define CP_WAIT1()  asm volatile("cp.async.wait_group 1;" ::: "memory")
#define CP_WAIT0()  asm volatile("cp.async.wait_group 0;" ::: "memory")
#define BAR_SYNC(id, cnt) asm volatile("bar.sync %0, %1;" :: "r"(id), "r"(cnt) : "memory")
__device__ __forceinline__ uint32_t sptr(const void* p) {
    return (uint32_t)__cvta_generic_to_shared(p);
}
__device__ __forceinline__ uint32_t pack2(float a, float b) {
    __half2 h = __floats2half2_rn(a, b);
    return *reinterpret_cast<uint32_t*>(&h);
}
__device__ __forceinline__ float sthr(float z) {
    return (z > LAM) ? (z - LAM) : ((z < -LAM) ? (z + LAM) : 0.f);
}

// ---------------- prep ----------------
__device__ __forceinline__ float casv(int m, int k) {
    float s, c;
    sincospif((float)((m*k) & 127) * (1.0f/64.0f), &s, &c);
    return c + s;
}
__global__ void prep_kernel(const float* __restrict__ w1, const float* __restrict__ b1,
                            const float* __restrict__ w2, const float* __restrict__ b2) {
    int t = blockIdx.x * blockDim.x + threadIdx.x;
    if (t < 8*8*32) {
        int lane = t & 31, ks = (t >> 5) & 7, mt = t >> 8;
        int g = lane >> 2, tig = lane & 3;
        int m0 = mt*16 + g, k0 = ks*16 + 2*tig;
        uint4 v;
        v.x = pack2(casv(m0, k0),     casv(m0, k0+1));
        v.y = pack2(casv(m0+8, k0),   casv(m0+8, k0+1));
        v.z = pack2(casv(m0, k0+8),   casv(m0, k0+9));
        v.w = pack2(casv(m0+8, k0+8), casv(m0+8, k0+9));
        g_casPH[t] = v;
    }
    if (t < NB*BS*HID) {
        g_w1h[t] = __float2half(w1[t] + w1[NB*BS*HID + t]);
        g_w2h[t] = __float2half(w2[t] + w2[NB*HID*BS + t]);
    }
    if (t < NB*HID) g_b1s[t] = b1[t];
    if (t < NB*BS)  g_b2s[t] = b2[t];
}

extern __shared__ uint32_t smu[];

// ---------------------------------------------------------------------------
// casmul_f2h: pass 1 (validated). OUT_h = cas @ IN_f. smem = 18432 B.
// ---------------------------------------------------------------------------
__global__ __launch_bounds__(256, 2)
void casmul_f2h(const float* __restrict__ in, __half* __restrict__ out,
                int ncols, int total) {
    char* bS = (char*)smu;
    const int tid = threadIdx.x;
    const int w = tid >> 5, lane = tid & 31;
    const int g = lane >> 2, tig = lane & 3;
    const int l15 = lane & 15, lc8 = (lane >> 4) * 8;
    const int ntn = ncols >> 6;

    uint4 A[8];
    #pragma unroll
    for (int ks = 0; ks < 8; ks++)
        A[ks] = __ldg(&g_casPH[(w*8 + ks)*32 + lane]);

    float4 pf[8];
    int t = blockIdx.x;
    {
        int bt = t / ntn, nb = t - bt*ntn;
        const float* src = in + (size_t)bt*128u*(size_t)ncols + nb*64;
        #pragma unroll
        for (int i = 0; i < 8; i++) {
            int idx = i*256 + tid, k = idx >> 4, n4 = (idx & 15) << 2;
            pf[i] = *(const float4*)(src + (size_t)k*(size_t)ncols + n4);
        }
    }

    for (; t < total; t += gridDim.x) {
        __syncthreads();
        #pragma unroll
        for (int i = 0; i < 8; i++) {
            int idx = i*256 + tid, k = idx >> 4, n4 = (idx & 15) << 2;
            uint2 u;
            u.x = pack2(pf[i].x, pf[i].y);
            u.y = pack2(pf[i].z, pf[i].w);
            *(uint2*)(bS + k*144 + n4*2) = u;
        }
        __syncthreads();

        int tn = t + gridDim.x;
        if (tn < total) {
            int bt = tn / ntn, nb = tn - bt*ntn;
            const float* src = in + (size_t)bt*128u*(size_t)ncols + nb*64;
            #pragma unroll
            for (int i = 0; i < 8; i++) {
                int idx = i*256 + tid, k = idx >> 4, n4 = (idx & 15) << 2;
                pf[i] = *(const float4*)(src + (size_t)k*(size_t)ncols + n4);
            }
        }

        float acc[8][4];
        #pragma unroll
        for (int i = 0; i < 8; i++)
            #pragma unroll
            for (int j = 0; j < 4; j++) acc[i][j] = 0.f;

        #pragma unroll
        for (int ks = 0; ks < 8; ks++) {
            #pragma unroll
            for (int nq = 0; nq < 4; nq++) {
                uint32_t b[4];
                ldsm4t(b, sptr(bS + (ks*16 + l15)*144 + (nq*16 + lc8)*2));
                mma16(acc[nq*2  ], A[ks].x, A[ks].y, A[ks].z, A[ks].w, b[0], b[1]);
                mma16(acc[nq*2+1], A[ks].x, A[ks].y, A[ks].z, A[ks].w, b[2], b[3]);
            }
        }

        __syncthreads();
        #pragma unroll
        for (int nf = 0; nf < 8; nf++)
            #pragma unroll
            for (int r = 0; r < 2; r++) {
                int row = w*16 + g + r*8;
                *(uint32_t*)(bS + row*128 + ((nf ^ g) << 4) + tig*4) =
                    pack2(acc[nf][r*2], acc[nf][r*2+1]);
            }
        __syncwarp();
        {
            int bt = t / ntn, nb = t - bt*ntn;
            const size_t base = (size_t)bt*128u*(size_t)ncols + nb*64;
            #pragma unroll
            for (int i = 0; i < 4; i++) {
                int row = w*16 + (lane >> 3) + i*4;
                int q = lane & 7;
                uint4 v = *(uint4*)(bS + row*128 + ((q ^ (row & 7)) << 4));
                *(uint4*)(out + base + (size_t)row*(size_t)ncols + q*8) = v;
            }
        }
    }
}

// ---------------------------------------------------------------------------
// casmul_h2f: pass 5 (validated). OUT_f = scale*(cas @ IN_h) + add_f.
// B + residual cp.async double-buffered. smem = 106496 B.
// ---------------------------------------------------------------------------
__global__ __launch_bounds__(256, 2)
void casmul_h2f(const __half* __restrict__ in, float* __restrict__ out,
                const float* __restrict__ addsrc, float scale, int ncols, int total) {
    char* bS0 = (char*)smu;
    char* bS1 = bS0 + 18432;
    char* rS0 = bS1 + 18432;
    char* rS1 = rS0 + 34816;
    const int tid = threadIdx.x;
    const int w = tid >> 5, lane = tid & 31;
    const int g = lane >> 2, tig = lane & 3;
    const int l15 = lane & 15, lc8 = (lane >> 4) * 8;
    const int mw = w & 3, nw = w >> 2;
    const int ntn = ncols >> 6;

    uint4 A[2][8];
    #pragma unroll
    for (int mf = 0; mf < 2; mf++)
        #pragma unroll
        for (int ks = 0; ks < 8; ks++)
            A[mf][ks] = __ldg(&g_casPH[((mw*2 + mf)*8 + ks)*32 + lane]);

    int t = blockIdx.x;
    {
        int bt = t / ntn, nb = t - bt*ntn;
        const size_t base = (size_t)bt*128u*(size_t)ncols + nb*64;
        const __half* src = in + base;
        #pragma unroll
        for (int i = 0; i < 4; i++) {
            int idx = i*256 + tid, k = idx >> 3, seg = idx & 7;
            cp16(sptr(bS0 + k*144 + seg*16), src + (size_t)k*(size_t)ncols + seg*8);
        }
        const float* rsrc = addsrc + base;
        #pragma unroll
        for (int i = 0; i < 8; i++) {
            int idx = i*256 + tid, k = idx >> 4, seg = idx & 15;
            cp16(sptr(rS0 + k*272 + seg*16), rsrc + (size_t)k*(size_t)ncols + seg*4);
        }
        CP_COMMIT();
    }

    int buf = 0;
    for (; t < total; t += gridDim.x) {
        int tn = t + gridDim.x;
        if (tn < total) {
            char* bN = buf ? bS0 : bS1;
            char* rN = buf ? rS0 : rS1;
            int bt = tn / ntn, nb = tn - bt*ntn;
            const size_t base = (size_t)bt*128u*(size_t)ncols + nb*64;
            const __half* src = in + base;
            #pragma unroll
            for (int i = 0; i < 4; i++) {
                int idx = i*256 + tid, k = idx >> 3, seg = idx & 7;
                cp16(sptr(bN + k*144 + seg*16), src + (size_t)k*(size_t)ncols + seg*8);
            }
            const float* rsrc = addsrc + base;
            #pragma unroll
            for (int i = 0; i < 8; i++) {
                int idx = i*256 + tid, k = idx >> 4, seg = idx & 15;
                cp16(sptr(rN + k*272 + seg*16), rsrc + (size_t)k*(size_t)ncols + seg*4);
            }
            CP_COMMIT();
            CP_WAIT1();
        } else {
            CP_WAIT0();
        }
        __syncthreads();

        const char* bS = buf ? bS1 : bS0;
        const char* rS = buf ? rS1 : rS0;
        float acc[2][4][4];
        #pragma unroll
        for (int a = 0; a < 2; a++)
            #pragma unroll
            for (int b = 0; b < 4; b++)
                #pragma unroll
                for (int c = 0; c < 4; c++) acc[a][b][c] = 0.f;

        #pragma unroll
        for (int ks = 0; ks < 8; ks++) {
            #pragma unroll
            for (int nq = 0; nq < 2; nq++) {
                uint32_t b[4];
                ldsm4t(b, sptr(bS + (ks*16 + l15)*144 + (nw*32 + nq*16 + lc8)*2));
                #pragma unroll
                for (int mf = 0; mf < 2; mf++) {
                    mma16(acc[mf][nq*2  ], A[mf][ks].x, A[mf][ks].y, A[mf][ks].z, A[mf][ks].w, b[0], b[1]);
                    mma16(acc[mf][nq*2+1], A[mf][ks].x, A[mf][ks].y, A[mf][ks].z, A[mf][ks].w, b[2], b[3]);
                }
            }
        }

        {
            int bt = t / ntn, nb = t - bt*ntn;
            const size_t base = (size_t)bt*128u*(size_t)ncols + nb*64;
            #pragma unroll
            for (int mf = 0; mf < 2; mf++)
                #pragma unroll
                for (int nf = 0; nf < 4; nf++) {
                    int col = nw*32 + nf*8 + tig*2;
                    #pragma unroll
                    for (int r = 0; r < 2; r++) {
                        int row = mw*32 + mf*16 + g + r*8;
                        float2 rr = *(const float2*)(rS + row*272 + col*4);
                        float2 v;
                        v.x = acc[mf][nf][r*2  ] * scale + rr.x;
                        v.y = acc[mf][nf][r*2+1] * scale + rr.y;
                        *(float2*)&out[base + (size_t)row*(size_t)ncols + col] = v;
                    }
                }
        }
        __syncthreads();
        buf ^= 1;
    }
}

// ---------------------------------------------------------------------------
// fused_h: round-12 structure (4 chunks of 64 hidden, weights staged at chunk
// top). ONLY change vs r12: the O1->GEMM2 ordering uses a named barrier over
// the mw warp-pair (64 threads) instead of a CTA-wide __syncthreads.
// smem = 89088 B -> 2 CTAs/SM.
// ---------------------------------------------------------------------------
__global__ __launch_bounds__(256, 2)
void fused_h(const __half* __restrict__ in, __half* __restrict__ out) {
    char* buf = (char*)smu;                  // 34816
    char* O1  = buf + 34816;                 // 18432
    char* Wb1 = O1 + 18432;                  // 18432
    char* Wb2 = Wb1 + 18432;                 // 17408

    const int tid  = threadIdx.x;
    const int bI   = blockIdx.x >> 7;
    const int wcol = blockIdx.x & 127;
    const int blk  = blockIdx.y;
    const size_t gbase = ((size_t)(bI*128)*128u + (size_t)wcol)*1024u + (size_t)blk*128u;

    const __half* W1 = g_w1h + blk*BS*HID;
    const __half* W2 = g_w2h + blk*HID*BS;

    // group 0: X tile
    #pragma unroll
    for (int i = 0; i < 8; i++) {
        int idx = i*256 + tid, h = idx >> 4, seg = idx & 15;
        cp16(sptr(buf + h*272 + seg*16), in + gbase + (size_t)h*131072u + seg*8);
    }
    CP_COMMIT();
    // group 1: chunk-0 weights
    #pragma unroll
    for (int i = 0; i < 4; i++) {
        int idx = i*256 + tid, k = idx >> 3, seg = idx & 7;
        cp16(sptr(Wb1 + k*144 + seg*16), W1 + k*HID + seg*8);
    }
    #pragma unroll
    for (int i = 0; i < 4; i++) {
        int idx = i*256 + tid, k = idx >> 4, seg = idx & 15;
        cp16(sptr(Wb2 + k*272 + seg*16), W2 + (size_t)k*BS + seg*8);
    }
    CP_COMMIT();
    CP_WAIT1();   // X ready; chunk-0 weights still in flight

    const int wid = tid >> 5, lane = tid & 31;
    const int g = lane >> 2, tig = lane & 3;
    const int mw = wid & 3, nw = wid >> 2;
    const int l15 = lane & 15, lc8 = (lane >> 4) * 8;
    const int m0 = mw*32;
    __syncthreads();

    {   // ---- T = cas @ X ----
        float acc[2][8][4];
        #pragma unroll
        for (int a = 0; a < 2; a++) for (int b = 0; b < 8; b++) for (int c = 0; c < 4; c++) acc[a][b][c] = 0.f;
        #pragma unroll
        for (int ks = 0; ks < 8; ks++) {
            uint4 A0 = __ldg(&g_casPH[((mw*2  )*8 + ks)*32 + lane]);
            uint4 A1 = __ldg(&g_casPH[((mw*2+1)*8 + ks)*32 + lane]);
            #pragma unroll
            for (int nq = 0; nq < 4; nq++) {
                uint32_t b[4];
                ldsm4t(b, sptr(buf + (ks*16 + l15)*272 + (nw*64 + nq*16 + lc8)*2));
                mma16(acc[0][nq*2  ], A0.x, A0.y, A0.z, A0.w, b[0], b[1]);
                mma16(acc[0][nq*2+1], A0.x, A0.y, A0.z, A0.w, b[2], b[3]);
                mma16(acc[1][nq*2  ], A1.x, A1.y, A1.z, A1.w, b[0], b[1]);
                mma16(acc[1][nq*2+1], A1.x, A1.y, A1.z, A1.w, b[2], b[3]);
            }
        }
        __syncthreads();
        #pragma unroll
        for (int mf = 0; mf < 2; mf++) for (int nf = 0; nf < 8; nf++) {
            int n = nw*64 + nf*8 + tig*2;
            #pragma unroll
            for (int r = 0; r < 2; r++) {
                int m = m0 + mf*16 + g + r*8;
                *(uint32_t*)(buf + m*272 + n*2) = pack2(acc[mf][nf][r*2], acc[mf][nf][r*2+1]);
            }
        }
        __syncthreads();
    }

    // ---- MLP: 4 chunks of 64 hidden ----
    float acc2[2][8][4];
    #pragma unroll
    for (int a = 0; a < 2; a++) for (int b = 0; b < 8; b++) for (int c = 0; c < 4; c++) acc2[a][b][c] = 0.f;

    #pragma unroll 1
    for (int ch = 0; ch < 4; ch++) {
        if (ch > 0) {
            #pragma unroll
            for (int i = 0; i < 4; i++) {
                int idx = i*256 + tid, k = idx >> 3, seg = idx & 7;
                cp16(sptr(Wb1 + k*144 + seg*16), W1 + k*HID + ch*64 + seg*8);
            }
            #pragma unroll
            for (int i = 0; i < 4; i++) {
                int idx = i*256 + tid, k = idx >> 4, seg = idx & 15;
                cp16(sptr(Wb2 + k*272 + seg*16), W2 + (size_t)(ch*64 + k)*BS + seg*8);
            }
            CP_COMMIT();
        }
        CP_WAIT0(); __syncthreads();

        // ---- GEMM1: [128,128]@[128,64], warp n-range 32 ----
        float acc1[2][4][4];
        #pragma unroll
        for (int a = 0; a < 2; a++) for (int b = 0; b < 4; b++) for (int c = 0; c < 4; c++) acc1[a][b][c] = 0.f;

        #pragma unroll
        for (int ks = 0; ks < 8; ks++) {
            uint32_t a0[4], a1[4];
            ldsm4(a0, sptr(buf + (m0      + l15)*272 + (ks*16 + lc8)*2));
            ldsm4(a1, sptr(buf + (m0 + 16 + l15)*272 + (ks*16 + lc8)*2));
            #pragma unroll
            for (int nq = 0; nq < 2; nq++) {
                uint32_t b[4];
                ldsm4t(b, sptr(Wb1 + (ks*16 + l15)*144 + (nw*32 + nq*16 + lc8)*2));
                mma16(acc1[0][nq*2  ], a0[0], a0[1], a0[2], a0[3], b[0], b[1]);
                mma16(acc1[0][nq*2+1], a0[0], a0[1], a0[2], a0[3], b[2], b[3]);
                mma16(acc1[1][nq*2  ], a1[0], a1[1], a1[2], a1[3], b[0], b[1]);
                mma16(acc1[1][nq*2+1], a1[0], a1[1], a1[2], a1[3], b[2], b[3]);
            }
        }

        // ---- bias + relu -> O1 [128][64] pitch 144 ----
        #pragma unroll
        for (int mf = 0; mf < 2; mf++) for (int nf = 0; nf < 4; nf++) {
            int nc = nw*32 + nf*8 + tig*2;
            float bx = g_b1s[blk*HID + ch*64 + nc];
            float by = g_b1s[blk*HID + ch*64 + nc + 1];
            #pragma unroll
            for (int r = 0; r < 2; r++) {
                int m = m0 + mf*16 + g + r*8;
                *(uint32_t*)(O1 + m*144 + nc*2) =
                    pack2(fmaxf(acc1[mf][nf][r*2] + bx, 0.f), fmaxf(acc1[mf][nf][r*2+1] + by, 0.f));
            }
        }
        // O1 rows mw*32..+31 are written/read only by the mw warp-pair {mw, mw+4}:
        // pairwise named barrier instead of CTA-wide sync.
        BAR_SYNC(1 + mw, 64);

        // ---- GEMM2 partial: [128,64]@[64,128], warp n-range 64 ----
        #pragma unroll
        for (int ks = 0; ks < 4; ks++) {
            uint32_t a0[4], a1[4];
            ldsm4(a0, sptr(O1 + (m0      + l15)*144 + (ks*16 + lc8)*2));
            ldsm4(a1, sptr(O1 + (m0 + 16 + l15)*144 + (ks*16 + lc8)*2));
            #pragma unroll
            for (int nq = 0; nq < 4; nq++) {
                uint32_t b[4];
                ldsm4t(b, sptr(Wb2 + (ks*16 + l15)*272 + (nw*64 + nq*16 + lc8)*2));
                mma16(acc2[0][nq*2  ], a0[0], a0[1], a0[2], a0[3], b[0], b[1]);
                mma16(acc2[0][nq*2+1], a0[0], a0[1], a0[2], a0[3], b[2], b[3]);
                mma16(acc2[1][nq*2  ], a1[0], a1[1], a1[2], a1[3], b[0], b[1]);
                mma16(acc2[1][nq*2+1], a1[0], a1[1], a1[2], a1[3], b[2], b[3]);
            }
        }
        __syncthreads();   // Wb/O1 reads done before next chunk restage
    }

    // ---- O2 = softthresh(acc2 + b2) -> buf ----
    #pragma unroll
    for (int mf = 0; mf < 2; mf++) for (int nf = 0; nf < 8; nf++) {
        int n = nw*64 + nf*8 + tig*2;
        float bx = g_b2s[blk*BS + n], by = g_b2s[blk*BS + n + 1];
        #pragma unroll
        for (int r = 0; r < 2; r++) {
            int m = m0 + mf*16 + g + r*8;
            *(uint32_t*)(buf + m*272 + n*2) =
                pack2(sthr(acc2[mf][nf][r*2] + bx), sthr(acc2[mf][nf][r*2+1] + by));
        }
    }
    __syncthreads();

    {   // ---- Z = cas @ O2 ----
        float acc[2][8][4];
        #pragma unroll
        for (int a = 0; a < 2; a++) for (int b = 0; b < 8; b++) for (int c = 0; c < 4; c++) acc[a][b][c] = 0.f;
        #pragma unroll
        for (int ks = 0; ks < 8; ks++) {
            uint4 A0 = __ldg(&g_casPH[((mw*2  )*8 + ks)*32 + lane]);
            uint4 A1 = __ldg(&g_casPH[((mw*2+1)*8 + ks)*32 + lane]);
            #pragma unroll
            for (int nq = 0; nq < 4; nq++) {
                uint32_t b[4];
                ldsm4t(b, sptr(buf + (ks*16 + l15)*272 + (nw*64 + nq*16 + lc8)*2));
                mma16(acc[0][nq*2  ], A0.x, A0.y, A0.z, A0.w, b[0], b[1]);
                mma16(acc[0][nq*2+1], A0.x, A0.y, A0.z, A0.w, b[2], b[3]);
                mma16(acc[1][nq*2  ], A1.x, A1.y, A1.z, A1.w, b[0], b[1]);
                mma16(acc[1][nq*2+1], A1.x, A1.y, A1.z, A1.w, b[2], b[3]);
            }
        }

        __syncthreads();   // all Z reads of buf done -> reuse buf as scratch (pitch 256B)
        #pragma unroll
        for (int mf = 0; mf < 2; mf++) for (int nf = 0; nf < 8; nf++) {
            #pragma unroll
            for (int r = 0; r < 2; r++) {
                int m = m0 + mf*16 + g + r*8;   // m&7 == g
                *(uint32_t*)(buf + m*256 + (((nw << 3) | (nf ^ g)) << 4) + tig*4) =
                    pack2(acc[mf][nf][r*2], acc[mf][nf][r*2+1]);
            }
        }
        __syncthreads();
        #pragma unroll
        for (int pass = 0; pass < 8; pass++) {
            int row = pass*16 + (tid >> 4);
            int q = tid & 15;
            int ch = (q & 8) | ((q & 7) ^ (row & 7));
            uint4 v = *(uint4*)(buf + row*256 + ch*16);
            *(uint4*)(out + gbase + (size_t)row*131072u + q*8) = v;
        }
    }
}

// ---------------------------------------------------------------------------
extern "C" void kernel_launch(void* const* d_in, const int* in_sizes, int n_in,
                              void* d_out, int out_size) {
    const float* x  = (const float*)d_in[0];
    const float* w1 = (const float*)d_in[1];
    const float* b1 = (const float*)d_in[2];
    const float* w2 = (const float*)d_in[3];
    const float* b2 = (const float*)d_in[4];
    float* out = (float*)d_out;

    void *p1, *p2;
    cudaGetSymbolAddress(&p1, g_bh1);
    cudaGetSymbolAddress(&p2, g_bh2);
    __half* bh1 = (__half*)p1;
    __half* bh2 = (__half*)p2;

    const int CAS1_SMEM = 18432;
    const int CAS2_SMEM = 2*18432 + 2*34816;               // 106496
    const int MID_SMEM  = 34816 + 18432 + 18432 + 17408;   // 89088
    cudaFuncSetAttribute(casmul_f2h, cudaFuncAttributeMaxDynamicSharedMemorySize, CAS1_SMEM);
    cudaFuncSetAttribute(casmul_h2f, cudaFuncAttributeMaxDynamicSharedMemorySize, CAS2_SMEM);
    cudaFuncSetAttribute(fused_h,    cudaFuncAttributeMaxDynamicSharedMemorySize, MID_SMEM);

    prep_kernel<<<1024, 256>>>(w1, b1, w2, b2);

    const int GRID = 296;
    const int T1 = (CC/64) * (BB*HH);      // 8192 tiles

    casmul_f2h<<<GRID, 256, CAS1_SMEM>>>(x, bh1, CC, T1);
    fused_h<<<dim3(BB*WW, NB), 256, MID_SMEM>>>(bh1, bh2);
    casmul_h2f<<<GRID, 256, CAS2_SMEM>>>(bh2, out, x, 1.0f/(HH*WW), CC, T1);
}